// round 2
// baseline (speedup 1.0000x reference)
#include <cuda_runtime.h>
#include <cuda_bf16.h>
#include <math.h>

// ---------------- problem constants ----------------
#define Bb   2
#define Ss   512
#define Dd   768
#define Hh   12
#define DHh  64
#define EAe  4
#define EFe  8
#define DFFf 3072
#define Kk   2
#define Nn   (Bb*Ss)          // 1024
#define CAP  160              // ceil(1.25*1024/8)

// ---------------- static device scratch ----------------
__device__ float g_h1[Nn*Dd];
__device__ float g_q [Nn*Dd];
__device__ float g_k [Nn*Dd];
__device__ float g_P [(size_t)Bb*Hh*Ss*Ss];
__device__ float g_v [(size_t)Hh*Bb*Ss*DHh];
__device__ float g_ao[(size_t)Hh*Bb*Ss*DHh];
__device__ float g_x1[Nn*Dd];
__device__ float g_h2[Nn*Dd];
__device__ int   g_aidx[Nn*Hh];
__device__ float g_hcnt[Hh*EAe];
__device__ int   g_tidx[Nn*Kk];
__device__ float g_tp [Nn*Kk];
__device__ int   g_pos[Nn*Kk];
__device__ float g_w  [Nn*Kk];
__device__ float g_ecnt[EFe];
__device__ float g_eimp[EFe];
__device__ float g_buf [(size_t)EFe*CAP*Dd];
__device__ float g_hmid[(size_t)EFe*CAP*DFFf];
__device__ float g_ybuf[(size_t)EFe*CAP*Dd];

// device-side pointer table (avoids any host symbol-address API)
__device__ __forceinline__ float* dev_ptr(int id) {
    switch (id) {
        case 0: return g_h1;  case 1: return g_q;   case 2: return g_k;
        case 3: return g_x1;  case 4: return g_h2;  case 5: return g_buf;
        case 6: return g_hmid; default: return g_ybuf;
    }
}

// ---------------- kernels ----------------
__global__ void zero_kernel() {
    size_t i = (size_t)blockIdx.x * blockDim.x + threadIdx.x;
    size_t tot = (size_t)EFe * CAP * Dd;
    for (; i < tot; i += (size_t)gridDim.x * blockDim.x) g_buf[i] = 0.f;
    if (blockIdx.x == 0) {
        if (threadIdx.x < Hh*EAe) g_hcnt[threadIdx.x] = 0.f;
        if (threadIdx.x < EFe) { g_ecnt[threadIdx.x] = 0.f; g_eimp[threadIdx.x] = 0.f; }
    }
}

// per-token layernorm over Dd. src_id<0 -> use xext, else device global.
__global__ void ln_kernel(const float* __restrict__ xext, const float* __restrict__ g,
                          const float* __restrict__ b, int src_id, int dst_id) {
    int n = blockIdx.x, tid = threadIdx.x;
    __shared__ float red[256];
    const float* xr = ((src_id >= 0) ? (const float*)dev_ptr(src_id) : xext) + (size_t)n * Dd;
    float* out = dev_ptr(dst_id);
    float s = 0.f;
    for (int d = tid; d < Dd; d += 256) s += xr[d];
    red[tid] = s; __syncthreads();
    for (int o = 128; o; o >>= 1) { if (tid < o) red[tid] += red[tid+o]; __syncthreads(); }
    float mu = red[0] / Dd; __syncthreads();
    float v = 0.f;
    for (int d = tid; d < Dd; d += 256) { float t = xr[d] - mu; v += t*t; }
    red[tid] = v; __syncthreads();
    for (int o = 128; o; o >>= 1) { if (tid < o) red[tid] += red[tid+o]; __syncthreads(); }
    float rstd = rsqrtf(red[0] / Dd + 1e-5f);
    for (int d = tid; d < Dd; d += 256)
        out[(size_t)n*Dd + d] = (xr[d] - mu) * rstd * g[d] + b[d];
}

// batched tiled GEMM: C[z] = A[z](MxK) @ B[z](KxN), optional relu.
// A and C are device globals (ids); B is an external weight pointer.
__global__ void gemm64(int Aid, const float* __restrict__ B, int Cid,
                       int M, int Nc, int Kd,
                       size_t sA, size_t sB, size_t sC, int relu) {
    const float* A = dev_ptr(Aid) + (size_t)blockIdx.z * sA;
    float*       C = dev_ptr(Cid) + (size_t)blockIdx.z * sC;
    B += (size_t)blockIdx.z * sB;
    __shared__ float As[16][64];
    __shared__ float Bs[16][65];
    int tid = threadIdx.x;
    int row0 = blockIdx.y * 64, col0 = blockIdx.x * 64;
    int tr = (tid >> 4) * 4, tc = (tid & 15) * 4;
    float acc[4][4] = {};
    for (int k0 = 0; k0 < Kd; k0 += 16) {
        #pragma unroll
        for (int i = 0; i < 4; i++) {
            int e = tid + i*256;
            int r = e >> 4, c = e & 15;
            int gr = row0 + r;
            As[c][r] = (gr < M) ? A[(size_t)gr*Kd + k0 + c] : 0.f;
        }
        #pragma unroll
        for (int i = 0; i < 4; i++) {
            int e = tid + i*256;
            int r = e >> 6, c = e & 63;
            Bs[r][c] = B[(size_t)(k0+r)*Nc + col0 + c];
        }
        __syncthreads();
        #pragma unroll
        for (int kk = 0; kk < 16; kk++) {
            float a0 = As[kk][tr], a1 = As[kk][tr+1], a2 = As[kk][tr+2], a3 = As[kk][tr+3];
            float b0 = Bs[kk][tc], b1 = Bs[kk][tc+1], b2 = Bs[kk][tc+2], b3 = Bs[kk][tc+3];
            acc[0][0] += a0*b0; acc[0][1] += a0*b1; acc[0][2] += a0*b2; acc[0][3] += a0*b3;
            acc[1][0] += a1*b0; acc[1][1] += a1*b1; acc[1][2] += a1*b2; acc[1][3] += a1*b3;
            acc[2][0] += a2*b0; acc[2][1] += a2*b1; acc[2][2] += a2*b2; acc[2][3] += a2*b3;
            acc[3][0] += a3*b0; acc[3][1] += a3*b1; acc[3][2] += a3*b2; acc[3][3] += a3*b3;
        }
        __syncthreads();
    }
    #pragma unroll
    for (int i = 0; i < 4; i++) {
        int gr = row0 + tr + i;
        if (gr >= M) continue;
        #pragma unroll
        for (int j = 0; j < 4; j++) {
            float v = acc[i][j];
            if (relu) v = fmaxf(v, 0.f);
            C[(size_t)gr*Nc + col0 + tc + j] = v;
        }
    }
}

// attention router: gate = h1 @ router_w (Dd x 48), argmax per head, count
__global__ void router_kernel(const float* __restrict__ rw) {
    int n = blockIdx.x, tid = threadIdx.x; // 64 threads
    __shared__ float gl[Hh*EAe];
    if (tid < Hh*EAe) {
        float acc = 0.f;
        const float* xr = g_h1 + (size_t)n * Dd;
        for (int d = 0; d < Dd; d++) acc += xr[d] * rw[(size_t)d*(Hh*EAe) + tid];
        gl[tid] = acc;
    }
    __syncthreads();
    if (tid < Hh) {
        float best = gl[tid*EAe]; int bi = 0;
        for (int j = 1; j < EAe; j++) { float v = gl[tid*EAe + j]; if (v > best) { best = v; bi = j; } }
        g_aidx[n*Hh + tid] = bi;
        atomicAdd(&g_hcnt[tid*EAe + bi], 1.0f);
    }
}

// scores + softmax -> P[b,h,s,t]
__global__ void attn_softmax(const float* __restrict__ mask) {
    int s = blockIdx.x, h = blockIdx.y, b = blockIdx.z;
    int tid = threadIdx.x;
    __shared__ float qs[DHh];
    __shared__ float sc[Ss];
    __shared__ float red[256];
    if (tid < DHh) qs[tid] = g_q[((size_t)(b*Ss + s))*Dd + h*DHh + tid];
    __syncthreads();
    float lmax = -1e30f;
    for (int t = tid; t < Ss; t += 256) {
        const float* kr = &g_k[((size_t)(b*Ss + t))*Dd + h*DHh];
        float acc = 0.f;
        #pragma unroll
        for (int d = 0; d < DHh; d++) acc += qs[d] * kr[d];
        float v = acc * 0.125f + mask[s*Ss + t];
        sc[t] = v;
        lmax = fmaxf(lmax, v);
    }
    red[tid] = lmax; __syncthreads();
    for (int o = 128; o; o >>= 1) { if (tid < o) red[tid] = fmaxf(red[tid], red[tid+o]); __syncthreads(); }
    float mx = red[0]; __syncthreads();
    float lsum = 0.f;
    for (int t = tid; t < Ss; t += 256) { float e = expf(sc[t] - mx); sc[t] = e; lsum += e; }
    red[tid] = lsum; __syncthreads();
    for (int o = 128; o; o >>= 1) { if (tid < o) red[tid] += red[tid+o]; __syncthreads(); }
    float inv = 1.f / red[0];
    float* Pr = &g_P[(((size_t)(b*Hh + h))*Ss + s)*Ss];
    for (int t = tid; t < Ss; t += 256) Pr[t] = sc[t] * inv;
}

// v_proj[h,b,s,e] = sum_d h1[b,s,h*64+d] * W_v[h, idx, d, e]
__global__ void vproj_kernel(const float* __restrict__ Wv) {
    int h = blockIdx.x, n = blockIdx.y;
    int b = n / Ss, s = n % Ss;
    int e = threadIdx.x; // 64
    __shared__ float xs[DHh];
    xs[e] = g_h1[(size_t)n*Dd + h*DHh + e];
    __syncthreads();
    int ia = g_aidx[n*Hh + h];
    const float* W = Wv + ((size_t)(h*EAe + ia)*DHh)*DHh;
    float acc = 0.f;
    #pragma unroll 8
    for (int d = 0; d < DHh; d++) acc += xs[d] * W[d*DHh + e];
    g_v[(((size_t)h*Bb + b)*Ss + s)*DHh + e] = acc;
}

// attn_out[h,b,t,d] = sum_s P[b,h,s,t] * v[h,b,s,d]   (TN gemm, causal skip)
// grid: (Ss/64, Hh, Bb), 256 threads, 4x4 micro-tile
__global__ void attnout_tn() {
    int t0 = blockIdx.x * 64, h = blockIdx.y, b = blockIdx.z;
    const float* P  = g_P + ((size_t)(b*Hh + h))*Ss*Ss;      // [s][t]
    const float* vb = g_v + (((size_t)h*Bb + b)*Ss)*DHh;     // [s][d]
    __shared__ float Ps[16][65];
    __shared__ float Vs[16][65];
    int tid = threadIdx.x;
    int tr = (tid >> 4) * 4, tc = (tid & 15) * 4;
    float acc[4][4] = {};
    for (int k0 = t0; k0 < Ss; k0 += 16) {
        #pragma unroll
        for (int i = 0; i < 4; i++) {
            int e = tid + i*256;
            int r = e >> 6, c = e & 63;
            Ps[r][c] = P[(size_t)(k0+r)*Ss + t0 + c];
            Vs[r][c] = vb[(size_t)(k0+r)*DHh + c];
        }
        __syncthreads();
        #pragma unroll
        for (int kk = 0; kk < 16; kk++) {
            float a0 = Ps[kk][tr], a1 = Ps[kk][tr+1], a2 = Ps[kk][tr+2], a3 = Ps[kk][tr+3];
            float b0 = Vs[kk][tc], b1 = Vs[kk][tc+1], b2 = Vs[kk][tc+2], b3 = Vs[kk][tc+3];
            acc[0][0] += a0*b0; acc[0][1] += a0*b1; acc[0][2] += a0*b2; acc[0][3] += a0*b3;
            acc[1][0] += a1*b0; acc[1][1] += a1*b1; acc[1][2] += a1*b2; acc[1][3] += a1*b3;
            acc[2][0] += a2*b0; acc[2][1] += a2*b1; acc[2][2] += a2*b2; acc[2][3] += a2*b3;
            acc[3][0] += a3*b0; acc[3][1] += a3*b1; acc[3][2] += a3*b2; acc[3][3] += a3*b3;
        }
        __syncthreads();
    }
    float* ao = g_ao + (((size_t)h*Bb + b)*Ss)*DHh;
    #pragma unroll
    for (int i = 0; i < 4; i++)
        #pragma unroll
        for (int j = 0; j < 4; j++)
            ao[(size_t)(t0 + tr + i)*DHh + tc + j] = acc[i][j];
}

// o_proj + residual: x1 = x + attn_out @ W_o[h, idx]
__global__ void oproj_kernel(const float* __restrict__ Wo, const float* __restrict__ x) {
    int h = blockIdx.x, n = blockIdx.y;
    int b = n / Ss, s = n % Ss;
    int e = threadIdx.x; // 64
    __shared__ float as_[DHh];
    as_[e] = g_ao[(((size_t)h*Bb + b)*Ss + s)*DHh + e];
    __syncthreads();
    int ia = g_aidx[n*Hh + h];
    const float* W = Wo + ((size_t)(h*EAe + ia)*DHh)*DHh;
    float acc = 0.f;
    #pragma unroll 8
    for (int d = 0; d < DHh; d++) acc += as_[d] * W[d*DHh + e];
    size_t o = (size_t)n*Dd + h*DHh + e;
    g_x1[o] = x[o] + acc;
}

// MoE gate: logits = h2 @ gate_w, top-2 + softmax
__global__ void moe_gate(const float* __restrict__ gw) {
    int n = blockIdx.x, tid = threadIdx.x; // 256
    __shared__ float logits[EFe];
    int e = tid >> 5, lane = tid & 31;
    const float* xr = g_h2 + (size_t)n * Dd;
    float acc = 0.f;
    for (int d = lane; d < Dd; d += 32) acc += xr[d] * gw[(size_t)d*EFe + e];
    for (int o = 16; o; o >>= 1) acc += __shfl_down_sync(0xffffffffu, acc, o);
    if (lane == 0) logits[e] = acc;
    __syncthreads();
    if (tid == 0) {
        int i1 = 0; float s1 = logits[0];
        for (int j = 1; j < EFe; j++) if (logits[j] > s1) { s1 = logits[j]; i1 = j; }
        int i2 = (i1 == 0) ? 1 : 0; float s2 = logits[i2];
        for (int j = 0; j < EFe; j++) { if (j == i1) continue; if (logits[j] > s2) { s2 = logits[j]; i2 = j; } }
        float e2 = expf(s2 - s1);
        float den = 1.f + e2;
        g_tidx[n*2] = i1; g_tidx[n*2+1] = i2;
        g_tp[n*2] = 1.f/den; g_tp[n*2+1] = e2/den;
    }
}

// sequential capacity scan (exact reproduction of jnp.cumsum ordering)
__global__ void scan_kernel() {
    if (threadIdx.x != 0 || blockIdx.x != 0) return;
    int cnt[EFe]; for (int e = 0; e < EFe; e++) cnt[e] = 0;
    for (int i = 0; i < Nn*Kk; i++) { int e = g_tidx[i]; g_pos[i] = cnt[e]++; }
    float c2[EFe] = {}, im[EFe] = {};
    for (int n = 0; n < Nn; n++) {
        float p0 = g_tp[2*n], p1 = g_tp[2*n+1];
        bool k0 = g_pos[2*n]   < CAP;
        bool k1 = g_pos[2*n+1] < CAP;
        float q0 = k0 ? p0 : 0.f, q1 = k1 ? p1 : 0.f;
        float den = q0 + q1 + 1e-9f;
        float w0 = q0 / den, w1 = q1 / den;
        g_w[2*n] = w0; g_w[2*n+1] = w1;
        if (w0 > 0.f) c2[g_tidx[2*n]]   += 1.f;
        if (w1 > 0.f) c2[g_tidx[2*n+1]] += 1.f;
        im[g_tidx[2*n]]   += w0;
        im[g_tidx[2*n+1]] += w1;
    }
    for (int e = 0; e < EFe; e++) { g_ecnt[e] = c2[e]; g_eimp[e] = im[e]; }
}

// gather kept tokens into expert buffers
__global__ void gather_kernel() {
    int i = blockIdx.x;                 // N*K entries
    int p = g_pos[i];
    if (p >= CAP) return;
    int e = g_tidx[i], n = i >> 1;
    float* dst = g_buf + ((size_t)e*CAP + p)*Dd;
    const float* src = g_h2 + (size_t)n*Dd;
    for (int d = threadIdx.x; d < Dd; d += blockDim.x) dst[d] = src[d];
}

// combine: out = x1 + sum_k w_k * ybuf[expert,pos]
__global__ void combine_kernel(float* __restrict__ out) {
    int n = blockIdx.x;
    float w0 = g_w[2*n], w1 = g_w[2*n+1];
    int p0 = g_pos[2*n], p1 = g_pos[2*n+1];
    const float* y0 = g_ybuf + ((size_t)g_tidx[2*n]  *CAP + (p0 < CAP ? p0 : 0))*Dd;
    const float* y1 = g_ybuf + ((size_t)g_tidx[2*n+1]*CAP + (p1 < CAP ? p1 : 0))*Dd;
    for (int d = threadIdx.x; d < Dd; d += 256) {
        float acc = g_x1[(size_t)n*Dd + d];
        if (w0 > 0.f) acc += w0 * y0[d];
        if (w1 > 0.f) acc += w1 * y1[d];
        out[(size_t)n*Dd + d] = acc;
    }
}

__global__ void aux_kernel(float* __restrict__ out, int out_size) {
    if (threadIdx.x != 0 || blockIdx.x != 0) return;
    if (out_size <= Nn*Dd) return;
    float tot = 0.f;
    for (int i = 0; i < Hh*EAe; i++) tot += 0.01f * g_hcnt[i] / (float)Nn;
    float a1 = 0.f;
    for (int i = 0; i < Hh*EAe; i++) {
        float p = (0.01f * g_hcnt[i] / (float)Nn) / (tot + 1e-9f);
        a1 += p*p;
    }
    a1 *= (float)(EAe*Hh);
    float cs = 0.f, is = 0.f;
    for (int e = 0; e < EFe; e++) { cs += g_ecnt[e]; is += g_eimp[e]; }
    float a2 = 0.f;
    for (int e = 0; e < EFe; e++)
        a2 += (g_ecnt[e] / (cs + 1e-9f)) * (g_eimp[e] / (is + 1e-9f));
    a2 *= (float)EFe;
    out[Nn*Dd] = a1 + a2;
}

// ---------------- launch ----------------
extern "C" void kernel_launch(void* const* d_in, const int* in_sizes, int n_in,
                              void* d_out, int out_size) {
    const float* x      = (const float*)d_in[0];
    const float* mask   = (const float*)d_in[1];
    const float* ln1_g  = (const float*)d_in[2];
    const float* ln1_b  = (const float*)d_in[3];
    const float* ln2_g  = (const float*)d_in[4];
    const float* ln2_b  = (const float*)d_in[5];
    const float* W_q    = (const float*)d_in[6];
    const float* W_k    = (const float*)d_in[7];
    const float* W_v    = (const float*)d_in[8];
    const float* W_o    = (const float*)d_in[9];
    const float* rw     = (const float*)d_in[10];
    const float* gw     = (const float*)d_in[11];
    const float* W1     = (const float*)d_in[12];
    const float* W2     = (const float*)d_in[13];
    float* out = (float*)d_out;

    zero_kernel<<<256, 256>>>();

    // ln1: x -> h1(id 0)
    ln_kernel<<<Nn, 256>>>(x, ln1_g, ln1_b, -1, 0);

    // Q, K projections: h1(0) @ Wq -> q(1); h1(0) @ Wk -> k(2)
    dim3 gq(Dd/64, Nn/64, 1);
    gemm64<<<gq, 256>>>(0, W_q, 1, Nn, Dd, Dd, 0, 0, 0, 0);
    gemm64<<<gq, 256>>>(0, W_k, 2, Nn, Dd, Dd, 0, 0, 0, 0);

    // router + argmax
    router_kernel<<<Nn, 64>>>(rw);

    // scores + softmax
    attn_softmax<<<dim3(Ss, Hh, Bb), 256>>>(mask);

    // v projection (expert-gathered per token)
    vproj_kernel<<<dim3(Hh, Nn), DHh>>>(W_v);

    // attn_out = P^T @ V (TN gemm with causal skip)
    attnout_tn<<<dim3(Ss/64, Hh, Bb), 256>>>();

    // o projection + residual
    oproj_kernel<<<dim3(Hh, Nn), DHh>>>(W_o, x);

    // ln2: x1(3) -> h2(4)
    ln_kernel<<<Nn, 256>>>(nullptr, ln2_g, ln2_b, 3, 4);

    // MoE gate + top-2
    moe_gate<<<Nn, 256>>>(gw);

    // capacity scan (sequential, exact)
    scan_kernel<<<1, 1>>>();

    // gather into expert buffers
    gather_kernel<<<Nn*Kk, 256>>>();

    // expert FFN: hmid(6) = relu(buf(5) @ W1), ybuf(7) = hmid(6) @ W2
    dim3 g1(DFFf/64, (CAP+63)/64, EFe);
    gemm64<<<g1, 256>>>(5, W1, 6, CAP, DFFf, Dd,
                        (size_t)CAP*Dd, (size_t)Dd*DFFf, (size_t)CAP*DFFf, 1);
    dim3 g2(Dd/64, (CAP+63)/64, EFe);
    gemm64<<<g2, 256>>>(6, W2, 7, CAP, Dd, DFFf,
                        (size_t)CAP*DFFf, (size_t)DFFf*Dd, (size_t)CAP*Dd, 0);

    // combine + residual
    combine_kernel<<<Nn, 256>>>(out);

    // aux scalar
    aux_kernel<<<1, 1>>>(out, out_size);
}

// round 4
// speedup vs baseline: 1.1695x; 1.1695x over previous
#include <cuda_runtime.h>
#include <cuda_bf16.h>
#include <math.h>

// ---------------- problem constants ----------------
#define Bb   2
#define Ss   512
#define Dd   768
#define Hh   12
#define DHh  64
#define EAe  4
#define EFe  8
#define DFFf 3072
#define Kk   2
#define Nn   (Bb*Ss)          // 1024
#define CAP  160              // ceil(1.25*1024/8)

// ---------------- static device scratch ----------------
__device__ float g_h1[Nn*Dd];
__device__ float g_q [Nn*Dd];
__device__ float g_k [Nn*Dd];
__device__ float g_P [(size_t)Bb*Hh*Ss*Ss];
__device__ float g_v [(size_t)Hh*Bb*Ss*DHh];
__device__ float g_ao[(size_t)Hh*Bb*Ss*DHh];
__device__ float g_x1[Nn*Dd];
__device__ float g_h2[Nn*Dd];
__device__ int   g_aidx[Nn*Hh];
__device__ float g_hcnt[Hh*EAe];
__device__ int   g_tidx[Nn*Kk];
__device__ float g_tp [Nn*Kk];
__device__ int   g_pos[Nn*Kk];
__device__ float g_w  [Nn*Kk];
__device__ float g_ecnt[EFe];
__device__ float g_eimp[EFe];
__device__ float g_buf [(size_t)EFe*CAP*Dd];
__device__ float g_hmid[(size_t)EFe*CAP*DFFf];
__device__ float g_ybuf[(size_t)EFe*CAP*Dd];

// device-side pointer table (avoids any host symbol-address API)
__device__ __forceinline__ float* dev_ptr(int id) {
    switch (id) {
        case 0: return g_h1;  case 1: return g_q;   case 2: return g_k;
        case 3: return g_x1;  case 4: return g_h2;  case 5: return g_buf;
        case 6: return g_hmid; default: return g_ybuf;
    }
}

// ---------------- kernels ----------------
__global__ void zero_kernel() {
    size_t i = (size_t)blockIdx.x * blockDim.x + threadIdx.x;
    size_t tot = (size_t)EFe * CAP * Dd;
    for (; i < tot; i += (size_t)gridDim.x * blockDim.x) g_buf[i] = 0.f;
    if (blockIdx.x == 0) {
        if (threadIdx.x < Hh*EAe) g_hcnt[threadIdx.x] = 0.f;
        if (threadIdx.x < EFe) { g_ecnt[threadIdx.x] = 0.f; g_eimp[threadIdx.x] = 0.f; }
    }
}

// per-token layernorm over Dd. src_id<0 -> use xext, else device global.
__global__ void ln_kernel(const float* __restrict__ xext, const float* __restrict__ g,
                          const float* __restrict__ b, int src_id, int dst_id) {
    int n = blockIdx.x, tid = threadIdx.x;
    __shared__ float red[256];
    const float* xr = ((src_id >= 0) ? (const float*)dev_ptr(src_id) : xext) + (size_t)n * Dd;
    float* out = dev_ptr(dst_id);
    float s = 0.f;
    for (int d = tid; d < Dd; d += 256) s += xr[d];
    red[tid] = s; __syncthreads();
    for (int o = 128; o; o >>= 1) { if (tid < o) red[tid] += red[tid+o]; __syncthreads(); }
    float mu = red[0] / Dd; __syncthreads();
    float v = 0.f;
    for (int d = tid; d < Dd; d += 256) { float t = xr[d] - mu; v += t*t; }
    red[tid] = v; __syncthreads();
    for (int o = 128; o; o >>= 1) { if (tid < o) red[tid] += red[tid+o]; __syncthreads(); }
    float rstd = rsqrtf(red[0] / Dd + 1e-5f);
    for (int d = tid; d < Dd; d += 256)
        out[(size_t)n*Dd + d] = (xr[d] - mu) * rstd * g[d] + b[d];
}

// Vectorized, register-double-buffered 64x64x16 SGEMM.
// C[z] = A[z](MxK) @ B[z](KxN), optional relu.
// If B2 != null, blockIdx.z==1 selects (B2, Cid2) instead of batching (QK fusion).
__global__ __launch_bounds__(256, 2)
void gemm64v(int Aid, const float* __restrict__ B, int Cid,
             const float* __restrict__ B2, int Cid2,
             int M, int Nc, int Kd,
             size_t sA, size_t sB, size_t sC, int relu) {
    if (B2 != nullptr && blockIdx.z == 1) { B = B2; Cid = Cid2; }
    const float* A = dev_ptr(Aid) + (size_t)blockIdx.z * sA;
    float*       C = dev_ptr(Cid) + (size_t)blockIdx.z * sC;
    B += (size_t)blockIdx.z * sB;

    __shared__ float As[16][64];   // [k][m]
    __shared__ float Bs[16][64];   // [k][n]
    int tid = threadIdx.x;
    int row0 = blockIdx.y * 64, col0 = blockIdx.x * 64;
    int tr = (tid >> 4) * 4, tc = (tid & 15) * 4;

    // global-load mapping (one float4 per thread per operand tile)
    int ar = tid >> 2;            // 0..63   A row within tile
    int ac = (tid & 3) * 4;       // 0,4,8,12 A col (k) within tile
    int br = tid >> 4;            // 0..15   B row (k) within tile
    int bc = (tid & 15) * 4;      // 0..60   B col within tile

    float4 aS, bS;
    {   // preload tile 0
        int gr = row0 + ar;
        aS = (gr < M) ? *(const float4*)&A[(size_t)gr*Kd + ac]
                      : make_float4(0.f,0.f,0.f,0.f);
        bS = *(const float4*)&B[(size_t)br*Nc + col0 + bc];
    }
    As[ac+0][ar] = aS.x; As[ac+1][ar] = aS.y; As[ac+2][ar] = aS.z; As[ac+3][ar] = aS.w;
    *(float4*)&Bs[br][bc] = bS;
    __syncthreads();

    float acc[4][4] = {};
    for (int k0 = 0; k0 < Kd; k0 += 16) {
        bool more = (k0 + 16) < Kd;
        if (more) {
            int gr = row0 + ar;
            aS = (gr < M) ? *(const float4*)&A[(size_t)gr*Kd + k0 + 16 + ac]
                          : make_float4(0.f,0.f,0.f,0.f);
            bS = *(const float4*)&B[(size_t)(k0 + 16 + br)*Nc + col0 + bc];
        }
        #pragma unroll
        for (int kk = 0; kk < 16; kk++) {
            float4 av = *(const float4*)&As[kk][tr];
            float4 bv = *(const float4*)&Bs[kk][tc];
            acc[0][0] += av.x*bv.x; acc[0][1] += av.x*bv.y; acc[0][2] += av.x*bv.z; acc[0][3] += av.x*bv.w;
            acc[1][0] += av.y*bv.x; acc[1][1] += av.y*bv.y; acc[1][2] += av.y*bv.z; acc[1][3] += av.y*bv.w;
            acc[2][0] += av.z*bv.x; acc[2][1] += av.z*bv.y; acc[2][2] += av.z*bv.z; acc[2][3] += av.z*bv.w;
            acc[3][0] += av.w*bv.x; acc[3][1] += av.w*bv.y; acc[3][2] += av.w*bv.z; acc[3][3] += av.w*bv.w;
        }
        if (more) {
            __syncthreads();
            As[ac+0][ar] = aS.x; As[ac+1][ar] = aS.y; As[ac+2][ar] = aS.z; As[ac+3][ar] = aS.w;
            *(float4*)&Bs[br][bc] = bS;
            __syncthreads();
        }
    }
    #pragma unroll
    for (int i = 0; i < 4; i++) {
        int gr = row0 + tr + i;
        if (gr >= M) continue;
        float4 o;
        o.x = acc[i][0]; o.y = acc[i][1]; o.z = acc[i][2]; o.w = acc[i][3];
        if (relu) { o.x = fmaxf(o.x,0.f); o.y = fmaxf(o.y,0.f); o.z = fmaxf(o.z,0.f); o.w = fmaxf(o.w,0.f); }
        *(float4*)&C[(size_t)gr*Nc + col0 + tc] = o;
    }
}

// attention router: gate = h1 @ router_w (Dd x 48), argmax per head, count
__global__ void router_kernel(const float* __restrict__ rw) {
    int n = blockIdx.x, tid = threadIdx.x; // 64 threads
    __shared__ float gl[Hh*EAe];
    if (tid < Hh*EAe) {
        float acc = 0.f;
        const float* xr = g_h1 + (size_t)n * Dd;
        for (int d = 0; d < Dd; d++) acc += xr[d] * rw[(size_t)d*(Hh*EAe) + tid];
        gl[tid] = acc;
    }
    __syncthreads();
    if (tid < Hh) {
        float best = gl[tid*EAe]; int bi = 0;
        for (int j = 1; j < EAe; j++) { float v = gl[tid*EAe + j]; if (v > best) { best = v; bi = j; } }
        g_aidx[n*Hh + tid] = bi;
        atomicAdd(&g_hcnt[tid*EAe + bi], 1.0f);
    }
}

// scores + softmax -> P[b,h,s,t]
__global__ void attn_softmax(const float* __restrict__ mask) {
    int s = blockIdx.x, h = blockIdx.y, b = blockIdx.z;
    int tid = threadIdx.x;
    __shared__ float qs[DHh];
    __shared__ float sc[Ss];
    __shared__ float red[256];
    if (tid < DHh) qs[tid] = g_q[((size_t)(b*Ss + s))*Dd + h*DHh + tid];
    __syncthreads();
    float lmax = -1e30f;
    for (int t = tid; t < Ss; t += 256) {
        const float* kr = &g_k[((size_t)(b*Ss + t))*Dd + h*DHh];
        float acc = 0.f;
        #pragma unroll
        for (int d = 0; d < DHh; d++) acc += qs[d] * kr[d];
        float v = acc * 0.125f + mask[s*Ss + t];
        sc[t] = v;
        lmax = fmaxf(lmax, v);
    }
    red[tid] = lmax; __syncthreads();
    for (int o = 128; o; o >>= 1) { if (tid < o) red[tid] = fmaxf(red[tid], red[tid+o]); __syncthreads(); }
    float mx = red[0]; __syncthreads();
    float lsum = 0.f;
    for (int t = tid; t < Ss; t += 256) { float e = expf(sc[t] - mx); sc[t] = e; lsum += e; }
    red[tid] = lsum; __syncthreads();
    for (int o = 128; o; o >>= 1) { if (tid < o) red[tid] += red[tid+o]; __syncthreads(); }
    float inv = 1.f / red[0];
    float* Pr = &g_P[(((size_t)(b*Hh + h))*Ss + s)*Ss];
    for (int t = tid; t < Ss; t += 256) Pr[t] = sc[t] * inv;
}

// v_proj[h,b,s,e] = sum_d h1[b,s,h*64+d] * W_v[h, idx, d, e]
__global__ void vproj_kernel(const float* __restrict__ Wv) {
    int h = blockIdx.x, n = blockIdx.y;
    int b = n / Ss, s = n % Ss;
    int e = threadIdx.x; // 64
    __shared__ float xs[DHh];
    xs[e] = g_h1[(size_t)n*Dd + h*DHh + e];
    __syncthreads();
    int ia = g_aidx[n*Hh + h];
    const float* W = Wv + ((size_t)(h*EAe + ia)*DHh)*DHh;
    float acc = 0.f;
    #pragma unroll 8
    for (int d = 0; d < DHh; d++) acc += xs[d] * W[d*DHh + e];
    g_v[(((size_t)h*Bb + b)*Ss + s)*DHh + e] = acc;
}

// attn_out[h,b,t,d] = sum_s P[b,h,s,t] * v[h,b,s,d]   (TN gemm, causal skip)
__global__ __launch_bounds__(256, 2)
void attnout_tn() {
    int t0 = blockIdx.x * 64, h = blockIdx.y, b = blockIdx.z;
    const float* P  = g_P + ((size_t)(b*Hh + h))*Ss*Ss;      // [s][t]
    const float* vb = g_v + (((size_t)h*Bb + b)*Ss)*DHh;     // [s][d]
    __shared__ float Ps[16][64];
    __shared__ float Vs[16][64];
    int tid = threadIdx.x;
    int tr = (tid >> 4) * 4, tc = (tid & 15) * 4;
    int lr = tid >> 4;            // 0..15 tile row (k)
    int lc = (tid & 15) * 4;      // tile col

    float4 pS, vS;
    pS = *(const float4*)&P[(size_t)(t0 + lr)*Ss + t0 + lc];
    vS = *(const float4*)&vb[(size_t)(t0 + lr)*DHh + lc];
    *(float4*)&Ps[lr][lc] = pS;
    *(float4*)&Vs[lr][lc] = vS;
    __syncthreads();

    float acc[4][4] = {};
    for (int k0 = t0; k0 < Ss; k0 += 16) {
        bool more = (k0 + 16) < Ss;
        if (more) {
            pS = *(const float4*)&P[(size_t)(k0 + 16 + lr)*Ss + t0 + lc];
            vS = *(const float4*)&vb[(size_t)(k0 + 16 + lr)*DHh + lc];
        }
        #pragma unroll
        for (int kk = 0; kk < 16; kk++) {
            float4 av = *(const float4*)&Ps[kk][tr];
            float4 bv = *(const float4*)&Vs[kk][tc];
            acc[0][0] += av.x*bv.x; acc[0][1] += av.x*bv.y; acc[0][2] += av.x*bv.z; acc[0][3] += av.x*bv.w;
            acc[1][0] += av.y*bv.x; acc[1][1] += av.y*bv.y; acc[1][2] += av.y*bv.z; acc[1][3] += av.y*bv.w;
            acc[2][0] += av.z*bv.x; acc[2][1] += av.z*bv.y; acc[2][2] += av.z*bv.z; acc[2][3] += av.z*bv.w;
            acc[3][0] += av.w*bv.x; acc[3][1] += av.w*bv.y; acc[3][2] += av.w*bv.z; acc[3][3] += av.w*bv.w;
        }
        if (more) {
            __syncthreads();
            *(float4*)&Ps[lr][lc] = pS;
            *(float4*)&Vs[lr][lc] = vS;
            __syncthreads();
        }
    }
    float* ao = g_ao + (((size_t)h*Bb + b)*Ss)*DHh;
    #pragma unroll
    for (int i = 0; i < 4; i++) {
        float4 o; o.x = acc[i][0]; o.y = acc[i][1]; o.z = acc[i][2]; o.w = acc[i][3];
        *(float4*)&ao[(size_t)(t0 + tr + i)*DHh + tc] = o;
    }
}

// o_proj + residual: x1 = x + attn_out @ W_o[h, idx]
__global__ void oproj_kernel(const float* __restrict__ Wo, const float* __restrict__ x) {
    int h = blockIdx.x, n = blockIdx.y;
    int b = n / Ss, s = n % Ss;
    int e = threadIdx.x; // 64
    __shared__ float as_[DHh];
    as_[e] = g_ao[(((size_t)h*Bb + b)*Ss + s)*DHh + e];
    __syncthreads();
    int ia = g_aidx[n*Hh + h];
    const float* W = Wo + ((size_t)(h*EAe + ia)*DHh)*DHh;
    float acc = 0.f;
    #pragma unroll 8
    for (int d = 0; d < DHh; d++) acc += as_[d] * W[d*DHh + e];
    size_t o = (size_t)n*Dd + h*DHh + e;
    g_x1[o] = x[o] + acc;
}

// MoE gate: logits = h2 @ gate_w, top-2 + softmax
__global__ void moe_gate(const float* __restrict__ gw) {
    int n = blockIdx.x, tid = threadIdx.x; // 256
    __shared__ float logits[EFe];
    int e = tid >> 5, lane = tid & 31;
    const float* xr = g_h2 + (size_t)n * Dd;
    float acc = 0.f;
    for (int d = lane; d < Dd; d += 32) acc += xr[d] * gw[(size_t)d*EFe + e];
    for (int o = 16; o; o >>= 1) acc += __shfl_down_sync(0xffffffffu, acc, o);
    if (lane == 0) logits[e] = acc;
    __syncthreads();
    if (tid == 0) {
        int i1 = 0; float s1 = logits[0];
        for (int j = 1; j < EFe; j++) if (logits[j] > s1) { s1 = logits[j]; i1 = j; }
        int i2 = (i1 == 0) ? 1 : 0; float s2 = logits[i2];
        for (int j = 0; j < EFe; j++) { if (j == i1) continue; if (logits[j] > s2) { s2 = logits[j]; i2 = j; } }
        float e2 = expf(s2 - s1);
        float den = 1.f + e2;
        g_tidx[n*2] = i1; g_tidx[n*2+1] = i2;
        g_tp[n*2] = 1.f/den; g_tp[n*2+1] = e2/den;
    }
}

// sequential capacity scan on smem-staged data (exact cumsum ordering)
__global__ void scan_kernel() {
    __shared__ int   sidx[Nn*Kk];
    __shared__ float stp [Nn*Kk];
    __shared__ int   spos[Nn*Kk];
    __shared__ float sw  [Nn*Kk];
    int tid = threadIdx.x;
    for (int i = tid; i < Nn*Kk; i += 256) { sidx[i] = g_tidx[i]; stp[i] = g_tp[i]; }
    __syncthreads();
    if (tid == 0) {
        int cnt[EFe]; for (int e = 0; e < EFe; e++) cnt[e] = 0;
        for (int i = 0; i < Nn*Kk; i++) { int e = sidx[i]; spos[i] = cnt[e]++; }
        float c2[EFe] = {}, im[EFe] = {};
        for (int n = 0; n < Nn; n++) {
            float p0 = stp[2*n], p1 = stp[2*n+1];
            float q0 = (spos[2*n]   < CAP) ? p0 : 0.f;
            float q1 = (spos[2*n+1] < CAP) ? p1 : 0.f;
            float den = q0 + q1 + 1e-9f;
            float w0 = q0 / den, w1 = q1 / den;
            sw[2*n] = w0; sw[2*n+1] = w1;
            if (w0 > 0.f) c2[sidx[2*n]]   += 1.f;
            if (w1 > 0.f) c2[sidx[2*n+1]] += 1.f;
            im[sidx[2*n]]   += w0;
            im[sidx[2*n+1]] += w1;
        }
        for (int e = 0; e < EFe; e++) { g_ecnt[e] = c2[e]; g_eimp[e] = im[e]; }
    }
    __syncthreads();
    for (int i = tid; i < Nn*Kk; i += 256) { g_pos[i] = spos[i]; g_w[i] = sw[i]; }
}

// gather kept tokens into expert buffers
__global__ void gather_kernel() {
    int i = blockIdx.x;                 // N*K entries
    int p = g_pos[i];
    if (p >= CAP) return;
    int e = g_tidx[i], n = i >> 1;
    float* dst = g_buf + ((size_t)e*CAP + p)*Dd;
    const float* src = g_h2 + (size_t)n*Dd;
    for (int d = threadIdx.x; d < Dd; d += blockDim.x) dst[d] = src[d];
}

// combine: out = x1 + sum_k w_k * ybuf[expert,pos]
__global__ void combine_kernel(float* __restrict__ out) {
    int n = blockIdx.x;
    float w0 = g_w[2*n], w1 = g_w[2*n+1];
    int p0 = g_pos[2*n], p1 = g_pos[2*n+1];
    const float* y0 = g_ybuf + ((size_t)g_tidx[2*n]  *CAP + (p0 < CAP ? p0 : 0))*Dd;
    const float* y1 = g_ybuf + ((size_t)g_tidx[2*n+1]*CAP + (p1 < CAP ? p1 : 0))*Dd;
    for (int d = threadIdx.x; d < Dd; d += 256) {
        float acc = g_x1[(size_t)n*Dd + d];
        if (w0 > 0.f) acc += w0 * y0[d];
        if (w1 > 0.f) acc += w1 * y1[d];
        out[(size_t)n*Dd + d] = acc;
    }
}

__global__ void aux_kernel(float* __restrict__ out, int out_size) {
    if (threadIdx.x != 0 || blockIdx.x != 0) return;
    if (out_size <= Nn*Dd) return;
    float tot = 0.f;
    for (int i = 0; i < Hh*EAe; i++) tot += 0.01f * g_hcnt[i] / (float)Nn;
    float a1 = 0.f;
    for (int i = 0; i < Hh*EAe; i++) {
        float p = (0.01f * g_hcnt[i] / (float)Nn) / (tot + 1e-9f);
        a1 += p*p;
    }
    a1 *= (float)(EAe*Hh);
    float cs = 0.f, is = 0.f;
    for (int e = 0; e < EFe; e++) { cs += g_ecnt[e]; is += g_eimp[e]; }
    float a2 = 0.f;
    for (int e = 0; e < EFe; e++)
        a2 += (g_ecnt[e] / (cs + 1e-9f)) * (g_eimp[e] / (is + 1e-9f));
    a2 *= (float)EFe;
    out[Nn*Dd] = a1 + a2;
}

// ---------------- launch ----------------
extern "C" void kernel_launch(void* const* d_in, const int* in_sizes, int n_in,
                              void* d_out, int out_size) {
    const float* x      = (const float*)d_in[0];
    const float* mask   = (const float*)d_in[1];
    const float* ln1_g  = (const float*)d_in[2];
    const float* ln1_b  = (const float*)d_in[3];
    const float* ln2_g  = (const float*)d_in[4];
    const float* ln2_b  = (const float*)d_in[5];
    const float* W_q    = (const float*)d_in[6];
    const float* W_k    = (const float*)d_in[7];
    const float* W_v    = (const float*)d_in[8];
    const float* W_o    = (const float*)d_in[9];
    const float* rw     = (const float*)d_in[10];
    const float* gw     = (const float*)d_in[11];
    const float* W1     = (const float*)d_in[12];
    const float* W2     = (const float*)d_in[13];
    float* out = (float*)d_out;

    zero_kernel<<<256, 256>>>();

    // ln1: x -> h1(id 0)
    ln_kernel<<<Nn, 256>>>(x, ln1_g, ln1_b, -1, 0);

    // Fused Q,K projections: z=0 -> q(1) = h1 @ Wq, z=1 -> k(2) = h1 @ Wk
    dim3 gq(Dd/64, Nn/64, 2);
    gemm64v<<<gq, 256>>>(0, W_q, 1, W_k, 2, Nn, Dd, Dd, 0, 0, 0, 0);

    // router + argmax
    router_kernel<<<Nn, 64>>>(rw);

    // scores + softmax
    attn_softmax<<<dim3(Ss, Hh, Bb), 256>>>(mask);

    // v projection (expert-gathered per token)
    vproj_kernel<<<dim3(Hh, Nn), DHh>>>(W_v);

    // attn_out = P^T @ V (TN gemm with causal skip)
    attnout_tn<<<dim3(Ss/64, Hh, Bb), 256>>>();

    // o projection + residual
    oproj_kernel<<<dim3(Hh, Nn), DHh>>>(W_o, x);

    // ln2: x1(3) -> h2(4)
    ln_kernel<<<Nn, 256>>>(nullptr, ln2_g, ln2_b, 3, 4);

    // MoE gate + top-2
    moe_gate<<<Nn, 256>>>(gw);

    // capacity scan (sequential semantics, smem-staged)
    scan_kernel<<<1, 256>>>();

    // gather into expert buffers
    gather_kernel<<<Nn*Kk, 256>>>();

    // expert FFN: hmid(6) = relu(buf(5) @ W1), ybuf(7) = hmid(6) @ W2
    dim3 g1(DFFf/64, (CAP+63)/64, EFe);
    gemm64v<<<g1, 256>>>(5, W1, 6, nullptr, 0, CAP, DFFf, Dd,
                         (size_t)CAP*Dd, (size_t)Dd*DFFf, (size_t)CAP*DFFf, 1);
    dim3 g2(Dd/64, (CAP+63)/64, EFe);
    gemm64v<<<g2, 256>>>(6, W2, 7, nullptr, 0, CAP, Dd, DFFf,
                         (size_t)CAP*DFFf, (size_t)DFFf*Dd, (size_t)CAP*Dd, 0);

    // combine + residual
    combine_kernel<<<Nn, 256>>>(out);

    // aux scalar
    aux_kernel<<<1, 1>>>(out, out_size);
}